// round 16
// baseline (speedup 1.0000x reference)
#include <cuda_runtime.h>
#include <cuda_fp16.h>
#include <cstdint>

// ---------------------------------------------------------------------------
// Problem constants
// ---------------------------------------------------------------------------
#define BS_N        8192
#define NUM_CLASSES 400
#define DIM         768
#define M_TOTAL     (2 * BS_N)          // 16384 rows
#define LOGITS_ELEMS (M_TOTAL * NUM_CLASSES)
#define NPAIRS      (2 * BS_N)

// ---------------------------------------------------------------------------
// Scratch: fp16 A and fp16 W (calibrated rel_err 2.9e-4 << 1e-3)
// ---------------------------------------------------------------------------
__device__ __half g_Ah[(size_t)M_TOTAL * DIM];
__device__ __half g_Wh[(size_t)NUM_CLASSES * DIM];

#define NA_ELEMS (M_TOTAL * DIM)        // 12,582,912
#define NW_ELEMS (NUM_CLASSES * DIM)    // 307,200
#define SPLIT_GROUPS ((NA_ELEMS + NW_ELEMS) / 8)

// ---------------------------------------------------------------------------
// Split kernel: fp32 -> fp16 (A and W)
// ---------------------------------------------------------------------------
__global__ void __launch_bounds__(256) split_kernel(const float* __restrict__ inA,
                                                    const float* __restrict__ inW) {
    int g = blockIdx.x * 256 + threadIdx.x;
    if (g >= SPLIT_GROUPS) return;

    const float* in;
    __half* out;
    int i8;
    if (g < NA_ELEMS / 8) {
        in = inA; out = g_Ah; i8 = g * 8;
    } else {
        in = inW; out = g_Wh; i8 = (g - NA_ELEMS / 8) * 8;
    }

    float4 v0 = *reinterpret_cast<const float4*>(in + i8);
    float4 v1 = *reinterpret_cast<const float4*>(in + i8 + 4);
    float f[8] = {v0.x, v0.y, v0.z, v0.w, v1.x, v1.y, v1.z, v1.w};
    __half h[8];
    #pragma unroll
    for (int j = 0; j < 8; ++j) h[j] = __float2half_rn(f[j]);
    *reinterpret_cast<uint4*>(out + i8) = *reinterpret_cast<const uint4*>(h);
}

// ---------------------------------------------------------------------------
// HMMA GEMM (UNCHANGED from round 14): CTA 128 thr (4 warps), 128x80x64,
// warp tile 32x80 (2m x 10n), SW128 swizzle, ldmatrix, 2-stage cp.async,
// 4 CTAs/SM.
// ---------------------------------------------------------------------------
#define BM 128
#define BN 80
#define BK 64
#define NCHUNKS (DIM / BK)                // 12

#define SA_H 0
#define SB_H (SA_H + BM * 128)            // 16384
#define STAGE_B (SB_H + BN * 128)         // 26624
#define SMEM_GEMM_TOTAL (2 * STAGE_B)     // 53248

__device__ __forceinline__ uint32_t smem_u32(const void* p) {
    uint32_t a;
    asm("{ .reg .u64 t; cvta.to.shared.u64 t, %1; cvt.u32.u64 %0, t; }"
        : "=r"(a) : "l"(p));
    return a;
}

__device__ __forceinline__ void cp_async16(uint32_t s, const void* g) {
    asm volatile("cp.async.cg.shared.global [%0], [%1], 16;" :: "r"(s), "l"(g));
}

__device__ __forceinline__ void cp_commit() {
    asm volatile("cp.async.commit_group;" ::: "memory");
}

template <int N>
__device__ __forceinline__ void cp_wait() {
    asm volatile("cp.async.wait_group %0;" :: "n"(N) : "memory");
}

__device__ __forceinline__ void ldsm_x4(uint32_t& r0, uint32_t& r1,
                                        uint32_t& r2, uint32_t& r3, uint32_t a) {
    asm volatile("ldmatrix.sync.aligned.m8n8.x4.shared.b16 {%0,%1,%2,%3}, [%4];"
                 : "=r"(r0), "=r"(r1), "=r"(r2), "=r"(r3) : "r"(a));
}

__device__ __forceinline__ void mma16816(float* c, uint32_t a0, uint32_t a1,
                                         uint32_t a2, uint32_t a3,
                                         uint32_t b0, uint32_t b1) {
    asm volatile(
        "mma.sync.aligned.m16n8k16.row.col.f32.f16.f16.f32 "
        "{%0,%1,%2,%3}, {%4,%5,%6,%7}, {%8,%9}, {%0,%1,%2,%3};"
        : "+f"(c[0]), "+f"(c[1]), "+f"(c[2]), "+f"(c[3])
        : "r"(a0), "r"(a1), "r"(a2), "r"(a3), "r"(b0), "r"(b1));
}

__device__ __forceinline__ void load_stage(uint32_t sbase,
                                           const __half* Ah,
                                           const __half* Bh,
                                           int k0, int tid) {
    #pragma unroll
    for (int j = 0; j < 8; ++j) {
        int idx = tid + j * 128;
        int row = idx >> 3;
        int seg = idx & 7;
        size_t goff = (size_t)row * DIM + k0 + seg * 8;
        uint32_t sw = (uint32_t)row * 128 + (uint32_t)((seg ^ (row & 7)) << 4);
        cp_async16(sbase + SA_H + sw, Ah + goff);
    }
    #pragma unroll
    for (int j = 0; j < 5; ++j) {
        int idx = tid + j * 128;
        int row = idx >> 3;
        int seg = idx & 7;
        size_t goff = (size_t)row * DIM + k0 + seg * 8;
        uint32_t sw = (uint32_t)row * 128 + (uint32_t)((seg ^ (row & 7)) << 4);
        cp_async16(sbase + SB_H + sw, Bh + goff);
    }
    cp_commit();
}

__global__ void __launch_bounds__(128, 4) gemm_hmma_kernel(const float* __restrict__ bias,
                                                           float* __restrict__ C) {
    extern __shared__ char smem[];
    const int tid  = threadIdx.x;
    const int warp = tid >> 5;
    const int lane = tid & 31;
    const uint32_t sb = smem_u32(smem);

    const int m0 = blockIdx.y * BM;
    const int n0 = blockIdx.x * BN;

    const __half* Ah = g_Ah + (size_t)m0 * DIM;
    const __half* Bh = g_Wh + (size_t)n0 * DIM;

    float acc[2][10][4];
    #pragma unroll
    for (int mt = 0; mt < 2; ++mt)
        #pragma unroll
        for (int nt = 0; nt < 10; ++nt)
            #pragma unroll
            for (int j = 0; j < 4; ++j)
                acc[mt][nt][j] = 0.0f;

    const int lmat = lane >> 3;
    const int li   = lane & 7;
    const int a_rlo   = (lmat & 1) << 3;
    const int a_shalf = lmat >> 1;
    uint32_t a_row[2];
    #pragma unroll
    for (int mt = 0; mt < 2; ++mt)
        a_row[mt] = (uint32_t)(warp * 32 + mt * 16 + a_rlo + li) * 128;
    const int b_shalf = lmat & 1;
    uint32_t b_row[5];
    #pragma unroll
    for (int p = 0; p < 5; ++p)
        b_row[p] = (uint32_t)((p * 2 + (lmat >> 1)) * 8 + li) * 128;

    load_stage(sb, Ah, Bh, 0, tid);

    for (int c = 0; c < NCHUNKS; ++c) {
        const uint32_t cur = sb + (uint32_t)(c & 1) * STAGE_B;
        if (c + 1 < NCHUNKS) {
            load_stage(sb + (uint32_t)((c + 1) & 1) * STAGE_B, Ah, Bh,
                       (c + 1) * BK, tid);
            cp_wait<1>();
        } else {
            cp_wait<0>();
        }
        __syncthreads();

        #pragma unroll
        for (int k16 = 0; k16 < 4; ++k16) {
            const int s2 = k16 * 2;
            uint32_t ah[2][4];
            uint32_t axor = (uint32_t)((((s2 + a_shalf) ^ li) & 7) << 4);
            #pragma unroll
            for (int mt = 0; mt < 2; ++mt)
                ldsm_x4(ah[mt][0], ah[mt][1], ah[mt][2], ah[mt][3],
                        cur + SA_H + a_row[mt] + axor);
            uint32_t bh[10][2];
            uint32_t bxor = (uint32_t)((((s2 + b_shalf) ^ li) & 7) << 4);
            #pragma unroll
            for (int p = 0; p < 5; ++p)
                ldsm_x4(bh[p * 2][0], bh[p * 2][1], bh[p * 2 + 1][0], bh[p * 2 + 1][1],
                        cur + SB_H + b_row[p] + bxor);

            #pragma unroll
            for (int mt = 0; mt < 2; ++mt)
                #pragma unroll
                for (int nt = 0; nt < 10; ++nt)
                    mma16816(acc[mt][nt], ah[mt][0], ah[mt][1], ah[mt][2], ah[mt][3],
                             bh[nt][0], bh[nt][1]);
        }
        __syncthreads();
    }

    const int fr = lane >> 2;
    const int fc = (lane & 3) * 2;
    #pragma unroll
    for (int mt = 0; mt < 2; ++mt) {
        int row = m0 + warp * 32 + mt * 16 + fr;
        #pragma unroll
        for (int nt = 0; nt < 10; ++nt) {
            int col = n0 + nt * 8 + fc;
            float b0 = __ldg(bias + col);
            float b1 = __ldg(bias + col + 1);
            float2 v0 = make_float2(acc[mt][nt][0] + b0, acc[mt][nt][1] + b1);
            float2 v1 = make_float2(acc[mt][nt][2] + b0, acc[mt][nt][3] + b1);
            *reinterpret_cast<float2*>(&C[(size_t)row * NUM_CLASSES + col]) = v0;
            *reinterpret_cast<float2*>(&C[(size_t)(row + 8) * NUM_CLASSES + col]) = v1;
        }
    }
}

// ---------------------------------------------------------------------------
// Mask kernel — warp-autonomous. __launch_bounds__(256, 8) caps registers at
// 32 (restoring round-8's occupancy); rank-loop unroll removed (it was the
// register hog). FP expression trees verbatim — mask bits unchanged.
// ---------------------------------------------------------------------------
#define MW_WARPS 8

__device__ __forceinline__ float bilin_combine(const float* __restrict__ m,
                                               int rm0, int rm1, int c0, int c1,
                                               float fy, float fx) {
    float g00 = m[rm0 + c0];
    float g01 = m[rm0 + c1];
    float g10 = m[rm1 + c0];
    float g11 = m[rm1 + c1];
    return g00 * (1.0f - fy) * (1.0f - fx)
         + g01 * (1.0f - fy) * fx
         + g10 * fy * (1.0f - fx)
         + g11 * fy * fx;
}

__global__ void __launch_bounds__(256, 8) mask_kernel(const float* __restrict__ attn,
                                                      const int* __restrict__ pos,
                                                      float* __restrict__ mask_out) {
    const int w    = threadIdx.x >> 5;
    const int lane = threadIdx.x & 31;
    const int pid  = blockIdx.x * MW_WARPS + w;
    const int i    = pid >> 1;
    const int box  = pid & 1;

    __shared__ float m14[MW_WARPS][196];
    __shared__ float cm[MW_WARPS][196];
    __shared__ unsigned long long key[MW_WARPS][49];
    __shared__ int   keep[MW_WARPS][49];
    __shared__ float t_w[MW_WARPS][2][14];
    __shared__ float t_f0[MW_WARPS][2][14];
    __shared__ float t_f1[MW_WARPS][2][14];
    __shared__ int   t_i00[MW_WARPS][2][14];
    __shared__ int   t_i01[MW_WARPS][2][14];
    __shared__ int   t_i10[MW_WARPS][2][14];
    __shared__ int   t_i11[MW_WARPS][2][14];

    for (int t = lane; t < 196; t += 32)
        m14[w][t] = attn[i * 196 + t];

    if (lane < 28) {
        const int axis = lane / 14;
        const int idx  = lane - axis * 14;
        const int mul  = axis ? 1 : 14;

        const int* p = pos + i * 12;
        const int oT = p[box * 4 + 0];
        const int oL = p[box * 4 + 1];
        const int oHi = p[box * 4 + 2];
        const int oWi = p[box * 4 + 3];
        const int e0 = p[8], e1 = p[9], e2 = p[10], e3 = p[11];

        const float dimO = axis ? (float)oWi : (float)oHi;
        const float off  = axis ? (float)(oL - e1) : (float)(oT - e0);
        const float dimE = axis ? (float)e3 : (float)e2;

        float ty = fmaxf(((float)idx + 0.5f) * dimO / 14.0f - 0.5f, 0.0f);
        float y0 = floorf(ty);
        float y1 = fminf(y0 + 1.0f, dimO - 1.0f);
        t_w[w][axis][idx] = ty - y0;
        float Y0 = off + y0;
        float Y1 = off + y1;

        {
            float sy  = fmaxf((Y0 + 0.5f) * 14.0f / dimE - 0.5f, 0.0f);
            float r0f = floorf(sy);
            int r0 = (int)r0f;
            int r1 = min(r0 + 1, 13);
            t_f0[w][axis][idx]  = sy - r0f;
            t_i00[w][axis][idx] = r0 * mul;
            t_i01[w][axis][idx] = r1 * mul;
        }
        {
            float sy  = fmaxf((Y1 + 0.5f) * 14.0f / dimE - 0.5f, 0.0f);
            float r0f = floorf(sy);
            int r0 = (int)r0f;
            int r1 = min(r0 + 1, 13);
            t_f1[w][axis][idx]  = sy - r0f;
            t_i10[w][axis][idx] = r0 * mul;
            t_i11[w][axis][idx] = r1 * mul;
        }
    }
    __syncwarp();

    for (int t = lane; t < 196; t += 32) {
        const int y = t / 14;
        const int x = t - y * 14;

        float wy  = t_w[w][0][y];
        float wx  = t_w[w][1][x];
        float fyA = t_f0[w][0][y], fyB = t_f1[w][0][y];
        float fxA = t_f0[w][1][x], fxB = t_f1[w][1][x];
        int rA0 = t_i00[w][0][y], rA1 = t_i01[w][0][y];
        int rB0 = t_i10[w][0][y], rB1 = t_i11[w][0][y];
        int cA0 = t_i00[w][1][x], cA1 = t_i01[w][1][x];
        int cB0 = t_i10[w][1][x], cB1 = t_i11[w][1][x];

        float v00 = bilin_combine(m14[w], rA0, rA1, cA0, cA1, fyA, fxA);
        float v01 = bilin_combine(m14[w], rA0, rA1, cB0, cB1, fyA, fxB);
        float v10 = bilin_combine(m14[w], rB0, rB1, cA0, cA1, fyB, fxA);
        float v11 = bilin_combine(m14[w], rB0, rB1, cB0, cB1, fyB, fxB);

        cm[w][t] = v00 * (1.0f - wy) * (1.0f - wx)
                 + v01 * (1.0f - wy) * wx
                 + v10 * wy * (1.0f - wx)
                 + v11 * wy * wx;
    }
    __syncwarp();

    for (int t = lane; t < 49; t += 32) {
        const int qy = t / 7;
        const int qx = t - qy * 7;
        const float* c = cm[w];
        float s = (c[(2 * qy) * 14 + 2 * qx] + c[(2 * qy) * 14 + 2 * qx + 1]
                 + c[(2 * qy + 1) * 14 + 2 * qx] + c[(2 * qy + 1) * 14 + 2 * qx + 1]) * 0.25f;
        key[w][t] = ((unsigned long long)__float_as_uint(s) << 6)
                  | (unsigned long long)(48 - t);
    }
    __syncwarp();

    for (int t = lane; t < 49; t += 32) {
        const unsigned long long kv = key[w][t];
        int rank = 0;
        for (int j = 0; j < 49; ++j)          // no unroll: keeps regs low
            rank += (key[w][j] > kv);
        keep[w][t] = (rank < 25);
    }
    __syncwarp();

    for (int t = lane; t < 196; t += 32) {
        const int y = t / 14;
        const int x = t - y * 14;
        const int q = (y >> 1) * 7 + (x >> 1);
        mask_out[(box * BS_N + i) * 196 + t] = keep[w][q] ? 0.0f : 1.0f;
    }
}

// ---------------------------------------------------------------------------
// Launch: mask (s2) and split (main) start together at t=0; gemm follows
// split and backfills as mask drains.
// ---------------------------------------------------------------------------
extern "C" void kernel_launch(void* const* d_in, const int* in_sizes, int n_in,
                              void* d_out, int out_size) {
    const float* attn        = (const float*)d_in[0];   // [8192, 196]
    const int*   pos         = (const int*)d_in[1];     // [8192, 3, 4]
    const float* image_embed = (const float*)d_in[2];   // [16384, 768]
    const float* Wm          = (const float*)d_in[3];   // [400, 768]
    const float* bias        = (const float*)d_in[4];   // [400]

    float* logits = (float*)d_out;                      // [16384, 400]
    float* mask   = (float*)d_out + LOGITS_ELEMS;       // [16384, 196]

    cudaFuncSetAttribute(gemm_hmma_kernel,
                         cudaFuncAttributeMaxDynamicSharedMemorySize,
                         SMEM_GEMM_TOTAL);

    cudaStream_t s2 = nullptr;
    cudaEvent_t  e1 = nullptr, e2 = nullptr;
    bool forked =
        (cudaStreamCreateWithFlags(&s2, cudaStreamNonBlocking) == cudaSuccess) &&
        (cudaEventCreateWithFlags(&e1, cudaEventDisableTiming) == cudaSuccess) &&
        (cudaEventCreateWithFlags(&e2, cudaEventDisableTiming) == cudaSuccess);

    if (forked) {
        forked = (cudaEventRecord(e1, (cudaStream_t)0) == cudaSuccess) &&
                 (cudaStreamWaitEvent(s2, e1, 0) == cudaSuccess);
    }

    if (forked) {
        mask_kernel<<<NPAIRS / MW_WARPS, 256, 0, s2>>>(attn, pos, mask);
        cudaEventRecord(e2, s2);
    }

    split_kernel<<<(SPLIT_GROUPS + 255) / 256, 256>>>(image_embed, Wm);
    dim3 ggrid(NUM_CLASSES / BN, M_TOTAL / BM);          // (5, 128) = 640 CTAs
    gemm_hmma_kernel<<<ggrid, 128, SMEM_GEMM_TOTAL>>>(bias, logits);

    if (forked) {
        cudaStreamWaitEvent((cudaStream_t)0, e2, 0);
    } else {
        mask_kernel<<<NPAIRS / MW_WARPS, 256>>>(attn, pos, mask);
    }
}

// round 17
// speedup vs baseline: 1.0923x; 1.0923x over previous
#include <cuda_runtime.h>
#include <cuda_fp16.h>
#include <cstdint>

// ---------------------------------------------------------------------------
// Problem constants
// ---------------------------------------------------------------------------
#define BS_N        8192
#define NUM_CLASSES 400
#define DIM         768
#define M_TOTAL     (2 * BS_N)          // 16384 rows
#define LOGITS_ELEMS (M_TOTAL * NUM_CLASSES)
#define NPAIRS      (2 * BS_N)

// ---------------------------------------------------------------------------
// Scratch: fp16 A and fp16 W (calibrated rel_err 2.9e-4 << 1e-3)
// ---------------------------------------------------------------------------
__device__ __half g_Ah[(size_t)M_TOTAL * DIM];
__device__ __half g_Wh[(size_t)NUM_CLASSES * DIM];

#define NA_ELEMS (M_TOTAL * DIM)        // 12,582,912
#define NW_ELEMS (NUM_CLASSES * DIM)    // 307,200
#define SPLIT_GROUPS ((NA_ELEMS + NW_ELEMS) / 8)

// ---------------------------------------------------------------------------
// Split kernel: fp32 -> fp16 (A and W)  [best measured: 12.0us]
// ---------------------------------------------------------------------------
__global__ void __launch_bounds__(256) split_kernel(const float* __restrict__ inA,
                                                    const float* __restrict__ inW) {
    int g = blockIdx.x * 256 + threadIdx.x;
    if (g >= SPLIT_GROUPS) return;

    const float* in;
    __half* out;
    int i8;
    if (g < NA_ELEMS / 8) {
        in = inA; out = g_Ah; i8 = g * 8;
    } else {
        in = inW; out = g_Wh; i8 = (g - NA_ELEMS / 8) * 8;
    }

    float4 v0 = *reinterpret_cast<const float4*>(in + i8);
    float4 v1 = *reinterpret_cast<const float4*>(in + i8 + 4);
    float f[8] = {v0.x, v0.y, v0.z, v0.w, v1.x, v1.y, v1.z, v1.w};
    __half h[8];
    #pragma unroll
    for (int j = 0; j < 8; ++j) h[j] = __float2half_rn(f[j]);
    *reinterpret_cast<uint4*>(out + i8) = *reinterpret_cast<const uint4*>(h);
}

// ---------------------------------------------------------------------------
// HMMA GEMM (round 14, best measured ~37us): CTA 128 thr (4 warps),
// 128x80x64, warp tile 32x80, SW128 swizzle, ldmatrix, 2-stage cp.async,
// 4 CTAs/SM.
// ---------------------------------------------------------------------------
#define BM 128
#define BN 80
#define BK 64
#define NCHUNKS (DIM / BK)                // 12

#define SA_H 0
#define SB_H (SA_H + BM * 128)            // 16384
#define STAGE_B (SB_H + BN * 128)         // 26624
#define SMEM_GEMM_TOTAL (2 * STAGE_B)     // 53248

__device__ __forceinline__ uint32_t smem_u32(const void* p) {
    uint32_t a;
    asm("{ .reg .u64 t; cvta.to.shared.u64 t, %1; cvt.u32.u64 %0, t; }"
        : "=r"(a) : "l"(p));
    return a;
}

__device__ __forceinline__ void cp_async16(uint32_t s, const void* g) {
    asm volatile("cp.async.cg.shared.global [%0], [%1], 16;" :: "r"(s), "l"(g));
}

__device__ __forceinline__ void cp_commit() {
    asm volatile("cp.async.commit_group;" ::: "memory");
}

template <int N>
__device__ __forceinline__ void cp_wait() {
    asm volatile("cp.async.wait_group %0;" :: "n"(N) : "memory");
}

__device__ __forceinline__ void ldsm_x4(uint32_t& r0, uint32_t& r1,
                                        uint32_t& r2, uint32_t& r3, uint32_t a) {
    asm volatile("ldmatrix.sync.aligned.m8n8.x4.shared.b16 {%0,%1,%2,%3}, [%4];"
                 : "=r"(r0), "=r"(r1), "=r"(r2), "=r"(r3) : "r"(a));
}

__device__ __forceinline__ void mma16816(float* c, uint32_t a0, uint32_t a1,
                                         uint32_t a2, uint32_t a3,
                                         uint32_t b0, uint32_t b1) {
    asm volatile(
        "mma.sync.aligned.m16n8k16.row.col.f32.f16.f16.f32 "
        "{%0,%1,%2,%3}, {%4,%5,%6,%7}, {%8,%9}, {%0,%1,%2,%3};"
        : "+f"(c[0]), "+f"(c[1]), "+f"(c[2]), "+f"(c[3])
        : "r"(a0), "r"(a1), "r"(a2), "r"(a3), "r"(b0), "r"(b1));
}

__device__ __forceinline__ void load_stage(uint32_t sbase,
                                           const __half* Ah,
                                           const __half* Bh,
                                           int k0, int tid) {
    #pragma unroll
    for (int j = 0; j < 8; ++j) {
        int idx = tid + j * 128;
        int row = idx >> 3;
        int seg = idx & 7;
        size_t goff = (size_t)row * DIM + k0 + seg * 8;
        uint32_t sw = (uint32_t)row * 128 + (uint32_t)((seg ^ (row & 7)) << 4);
        cp_async16(sbase + SA_H + sw, Ah + goff);
    }
    #pragma unroll
    for (int j = 0; j < 5; ++j) {
        int idx = tid + j * 128;
        int row = idx >> 3;
        int seg = idx & 7;
        size_t goff = (size_t)row * DIM + k0 + seg * 8;
        uint32_t sw = (uint32_t)row * 128 + (uint32_t)((seg ^ (row & 7)) << 4);
        cp_async16(sbase + SB_H + sw, Bh + goff);
    }
    cp_commit();
}

__global__ void __launch_bounds__(128, 4) gemm_hmma_kernel(const float* __restrict__ bias,
                                                           float* __restrict__ C) {
    extern __shared__ char smem[];
    const int tid  = threadIdx.x;
    const int warp = tid >> 5;
    const int lane = tid & 31;
    const uint32_t sb = smem_u32(smem);

    const int m0 = blockIdx.y * BM;
    const int n0 = blockIdx.x * BN;

    const __half* Ah = g_Ah + (size_t)m0 * DIM;
    const __half* Bh = g_Wh + (size_t)n0 * DIM;

    float acc[2][10][4];
    #pragma unroll
    for (int mt = 0; mt < 2; ++mt)
        #pragma unroll
        for (int nt = 0; nt < 10; ++nt)
            #pragma unroll
            for (int j = 0; j < 4; ++j)
                acc[mt][nt][j] = 0.0f;

    const int lmat = lane >> 3;
    const int li   = lane & 7;
    const int a_rlo   = (lmat & 1) << 3;
    const int a_shalf = lmat >> 1;
    uint32_t a_row[2];
    #pragma unroll
    for (int mt = 0; mt < 2; ++mt)
        a_row[mt] = (uint32_t)(warp * 32 + mt * 16 + a_rlo + li) * 128;
    const int b_shalf = lmat & 1;
    uint32_t b_row[5];
    #pragma unroll
    for (int p = 0; p < 5; ++p)
        b_row[p] = (uint32_t)((p * 2 + (lmat >> 1)) * 8 + li) * 128;

    load_stage(sb, Ah, Bh, 0, tid);

    for (int c = 0; c < NCHUNKS; ++c) {
        const uint32_t cur = sb + (uint32_t)(c & 1) * STAGE_B;
        if (c + 1 < NCHUNKS) {
            load_stage(sb + (uint32_t)((c + 1) & 1) * STAGE_B, Ah, Bh,
                       (c + 1) * BK, tid);
            cp_wait<1>();
        } else {
            cp_wait<0>();
        }
        __syncthreads();

        #pragma unroll
        for (int k16 = 0; k16 < 4; ++k16) {
            const int s2 = k16 * 2;
            uint32_t ah[2][4];
            uint32_t axor = (uint32_t)((((s2 + a_shalf) ^ li) & 7) << 4);
            #pragma unroll
            for (int mt = 0; mt < 2; ++mt)
                ldsm_x4(ah[mt][0], ah[mt][1], ah[mt][2], ah[mt][3],
                        cur + SA_H + a_row[mt] + axor);
            uint32_t bh[10][2];
            uint32_t bxor = (uint32_t)((((s2 + b_shalf) ^ li) & 7) << 4);
            #pragma unroll
            for (int p = 0; p < 5; ++p)
                ldsm_x4(bh[p * 2][0], bh[p * 2][1], bh[p * 2 + 1][0], bh[p * 2 + 1][1],
                        cur + SB_H + b_row[p] + bxor);

            #pragma unroll
            for (int mt = 0; mt < 2; ++mt)
                #pragma unroll
                for (int nt = 0; nt < 10; ++nt)
                    mma16816(acc[mt][nt], ah[mt][0], ah[mt][1], ah[mt][2], ah[mt][3],
                             bh[nt][0], bh[nt][1]);
        }
        __syncthreads();
    }

    const int fr = lane >> 2;
    const int fc = (lane & 3) * 2;
    #pragma unroll
    for (int mt = 0; mt < 2; ++mt) {
        int row = m0 + warp * 32 + mt * 16 + fr;
        #pragma unroll
        for (int nt = 0; nt < 10; ++nt) {
            int col = n0 + nt * 8 + fc;
            float b0 = __ldg(bias + col);
            float b1 = __ldg(bias + col + 1);
            float2 v0 = make_float2(acc[mt][nt][0] + b0, acc[mt][nt][1] + b1);
            float2 v1 = make_float2(acc[mt][nt][2] + b0, acc[mt][nt][3] + b1);
            *reinterpret_cast<float2*>(&C[(size_t)row * NUM_CLASSES + col]) = v0;
            *reinterpret_cast<float2*>(&C[(size_t)(row + 8) * NUM_CLASSES + col]) = v1;
        }
    }
}

// ---------------------------------------------------------------------------
// Mask kernel — ROUND-9 BLOCK-STYLE VERSION (best measured: 46.0us,
// 32 regs natural, no spills). One block per image, 416 threads,
// box = tid/208; premultiplied row indices, packed-u64 rank keys.
// FP expression trees bit-exact verified.
// ---------------------------------------------------------------------------
__device__ __forceinline__ float bilin_combine(const float* __restrict__ m,
                                               int rm0, int rm1, int c0, int c1,
                                               float fy, float fx) {
    float g00 = m[rm0 + c0];
    float g01 = m[rm0 + c1];
    float g10 = m[rm1 + c0];
    float g11 = m[rm1 + c1];
    return g00 * (1.0f - fy) * (1.0f - fx)
         + g01 * (1.0f - fy) * fx
         + g10 * fy * (1.0f - fx)
         + g11 * fy * fx;
}

__global__ void __launch_bounds__(416) mask_kernel(const float* __restrict__ attn,
                                                   const int* __restrict__ pos,
                                                   float* __restrict__ mask_out) {
    const int i   = blockIdx.x;
    const int tid = threadIdx.x;

    __shared__ float m14[196];
    __shared__ float cm[2][196];
    __shared__ unsigned long long key[2][49];
    __shared__ int   keep[2][49];
    __shared__ float t_w[2][2][14];
    __shared__ float t_f0[2][2][14];
    __shared__ float t_f1[2][2][14];
    __shared__ int   t_i00[2][2][14];    // axis 0: r0*14 ; axis 1: c0
    __shared__ int   t_i01[2][2][14];
    __shared__ int   t_i10[2][2][14];
    __shared__ int   t_i11[2][2][14];

    if (tid < 196) m14[tid] = attn[i * 196 + tid];

    if (tid < 56) {
        const int s    = tid;
        const int pbox = s / 28;
        const int rem  = s - pbox * 28;
        const int axis = rem / 14;
        const int idx  = rem - axis * 14;
        const int mul  = axis ? 1 : 14;

        const int* p = pos + i * 12;
        const int oT = p[pbox * 4 + 0];
        const int oL = p[pbox * 4 + 1];
        const int oHi = p[pbox * 4 + 2];
        const int oWi = p[pbox * 4 + 3];
        const int e0 = p[8], e1 = p[9], e2 = p[10], e3 = p[11];

        const float dimO = axis ? (float)oWi : (float)oHi;
        const float off  = axis ? (float)(oL - e1) : (float)(oT - e0);
        const float dimE = axis ? (float)e3 : (float)e2;

        float ty = fmaxf(((float)idx + 0.5f) * dimO / 14.0f - 0.5f, 0.0f);
        float y0 = floorf(ty);
        float y1 = fminf(y0 + 1.0f, dimO - 1.0f);
        t_w[pbox][axis][idx] = ty - y0;
        float Y0 = off + y0;
        float Y1 = off + y1;

        {
            float sy  = fmaxf((Y0 + 0.5f) * 14.0f / dimE - 0.5f, 0.0f);
            float r0f = floorf(sy);
            int r0 = (int)r0f;
            int r1 = min(r0 + 1, 13);
            t_f0[pbox][axis][idx]  = sy - r0f;
            t_i00[pbox][axis][idx] = r0 * mul;
            t_i01[pbox][axis][idx] = r1 * mul;
        }
        {
            float sy  = fmaxf((Y1 + 0.5f) * 14.0f / dimE - 0.5f, 0.0f);
            float r0f = floorf(sy);
            int r0 = (int)r0f;
            int r1 = min(r0 + 1, 13);
            t_f1[pbox][axis][idx]  = sy - r0f;
            t_i10[pbox][axis][idx] = r0 * mul;
            t_i11[pbox][axis][idx] = r1 * mul;
        }
    }
    __syncthreads();

    const int box = tid / 208;
    const int t   = tid - box * 208;

    if (t < 196) {
        const int y = t / 14;
        const int x = t - y * 14;

        float wy  = t_w[box][0][y];
        float wx  = t_w[box][1][x];
        float fyA = t_f0[box][0][y], fyB = t_f1[box][0][y];
        float fxA = t_f0[box][1][x], fxB = t_f1[box][1][x];
        int rA0 = t_i00[box][0][y], rA1 = t_i01[box][0][y];
        int rB0 = t_i10[box][0][y], rB1 = t_i11[box][0][y];
        int cA0 = t_i00[box][1][x], cA1 = t_i01[box][1][x];
        int cB0 = t_i10[box][1][x], cB1 = t_i11[box][1][x];

        float v00 = bilin_combine(m14, rA0, rA1, cA0, cA1, fyA, fxA);
        float v01 = bilin_combine(m14, rA0, rA1, cB0, cB1, fyA, fxB);
        float v10 = bilin_combine(m14, rB0, rB1, cA0, cA1, fyB, fxA);
        float v11 = bilin_combine(m14, rB0, rB1, cB0, cB1, fyB, fxB);

        cm[box][t] = v00 * (1.0f - wy) * (1.0f - wx)
                   + v01 * (1.0f - wy) * wx
                   + v10 * wy * (1.0f - wx)
                   + v11 * wy * wx;
    }
    __syncthreads();

    if (t < 49) {
        const int qy = t / 7;
        const int qx = t - qy * 7;
        const float* c = cm[box];
        float s = (c[(2 * qy) * 14 + 2 * qx] + c[(2 * qy) * 14 + 2 * qx + 1]
                 + c[(2 * qy + 1) * 14 + 2 * qx] + c[(2 * qy + 1) * 14 + 2 * qx + 1]) * 0.25f;
        key[box][t] = ((unsigned long long)__float_as_uint(s) << 6)
                    | (unsigned long long)(48 - t);
    }
    __syncthreads();

    if (t < 49) {
        const unsigned long long kv = key[box][t];
        int rank = 0;
        #pragma unroll
        for (int j = 0; j < 49; ++j)
            rank += (key[box][j] > kv);
        keep[box][t] = (rank < 25);
    }
    __syncthreads();

    if (t < 196) {
        const int y = t / 14;
        const int x = t - y * 14;
        const int q = (y >> 1) * 7 + (x >> 1);
        mask_out[(box * BS_N + i) * 196 + t] = keep[box][q] ? 0.0f : 1.0f;
    }
}

// ---------------------------------------------------------------------------
// Launch: mask (s2) and split (main) start together at t=0; gemm follows
// split and backfills as mask drains. (Round-15 order, best measured.)
// ---------------------------------------------------------------------------
extern "C" void kernel_launch(void* const* d_in, const int* in_sizes, int n_in,
                              void* d_out, int out_size) {
    const float* attn        = (const float*)d_in[0];   // [8192, 196]
    const int*   pos         = (const int*)d_in[1];     // [8192, 3, 4]
    const float* image_embed = (const float*)d_in[2];   // [16384, 768]
    const float* Wm          = (const float*)d_in[3];   // [400, 768]
    const float* bias        = (const float*)d_in[4];   // [400]

    float* logits = (float*)d_out;                      // [16384, 400]
    float* mask   = (float*)d_out + LOGITS_ELEMS;       // [16384, 196]

    cudaFuncSetAttribute(gemm_hmma_kernel,
                         cudaFuncAttributeMaxDynamicSharedMemorySize,
                         SMEM_GEMM_TOTAL);

    cudaStream_t s2 = nullptr;
    cudaEvent_t  e1 = nullptr, e2 = nullptr;
    bool forked =
        (cudaStreamCreateWithFlags(&s2, cudaStreamNonBlocking) == cudaSuccess) &&
        (cudaEventCreateWithFlags(&e1, cudaEventDisableTiming) == cudaSuccess) &&
        (cudaEventCreateWithFlags(&e2, cudaEventDisableTiming) == cudaSuccess);

    if (forked) {
        forked = (cudaEventRecord(e1, (cudaStream_t)0) == cudaSuccess) &&
                 (cudaStreamWaitEvent(s2, e1, 0) == cudaSuccess);
    }

    if (forked) {
        mask_kernel<<<BS_N, 416, 0, s2>>>(attn, pos, mask);
        cudaEventRecord(e2, s2);
    }

    split_kernel<<<(SPLIT_GROUPS + 255) / 256, 256>>>(image_embed, Wm);
    dim3 ggrid(NUM_CLASSES / BN, M_TOTAL / BM);          // (5, 128) = 640 CTAs
    gemm_hmma_kernel<<<ggrid, 128, SMEM_GEMM_TOTAL>>>(bias, logits);

    if (forked) {
        cudaStreamWaitEvent((cudaStream_t)0, e2, 0);
    } else {
        mask_kernel<<<BS_N, 416>>>(attn, pos, mask);
    }
}